// round 2
// baseline (speedup 1.0000x reference)
#include <cuda_runtime.h>
#include <math.h>

#define BB 128          // batch rows
#define DD 128          // feature dim
#define NMAX (1u<<20)   // memory slots
#define GRID2 1024      // pass-2 blocks

// -------- device scratch (statically allocated; no cudaMalloc anywhere) ----
__device__ float g_state[BB*DD];                   // normalized state [B][D]
__device__ float g_Z[BB];                          // softmax denominators
__device__ float g_E[(size_t)NMAX*BB];             // exp weights [N][B] (512 MB)
__device__ float g_WSpart[(size_t)GRID2*BB*DD];    // per-block WS partials (64 MB)

// ---------------------------------------------------------------------------
// K0: normalize encoded_state rows, zero Z.   <<<1,128>>>
// ---------------------------------------------------------------------------
__global__ void k_norm(const float* __restrict__ st) {
    int b = threadIdx.x;
    float ss = 0.f;
    #pragma unroll 8
    for (int d = 0; d < DD; ++d) { float v = st[b*DD + d]; ss += v*v; }
    float nrm = sqrtf(ss);
    float inv = 1.0f / fmaxf(nrm, 1e-12f);
    #pragma unroll 8
    for (int d = 0; d < DD; ++d) g_state[b*DD + d] = st[b*DD + d] * inv;
    g_Z[b] = 0.f;
}

// ---------------------------------------------------------------------------
// K1: per 128-key tile: S = K_tile . state^T  (contraction over D),
//     E = exp((S-1)*invT), store E[N][B], accumulate Z[b].
//     256 threads, 8x8 micro-tile: n_i = tn + 16*i, b_j = 8*tb + j.
// ---------------------------------------------------------------------------
__global__ void __launch_bounds__(256, 2)
k_pass1(const float* __restrict__ keys, float invT) {
    __shared__ float Ks[128][36];   // keys tile, 32-wide d-chunk, pad->stride 36
    __shared__ float Ss[128][36];   // state tile (same chunk)
    __shared__ float zsm[128];

    const int tid = threadIdx.x;
    const int tn  = tid & 15;       // n-lane
    const int tb  = tid >> 4;       // b-group (0..15)
    const size_t n0 = (size_t)blockIdx.x * 128;

    float acc[8][8];
    #pragma unroll
    for (int i = 0; i < 8; ++i)
        #pragma unroll
        for (int j = 0; j < 8; ++j) acc[i][j] = 0.f;

    for (int d0 = 0; d0 < DD; d0 += 32) {
        // cooperative load: 128 rows x 32 floats for each operand
        #pragma unroll
        for (int t = 0; t < 4; ++t) {
            int idx = tid + 256*t;            // 0..1023
            int row = idx >> 3;
            int c4  = idx & 7;
            float4 kv = *(const float4*)(keys + (n0 + row)*DD + d0 + c4*4);
            *(float4*)&Ks[row][c4*4] = kv;
            float4 sv = *(const float4*)(g_state + row*DD + d0 + c4*4);
            *(float4*)&Ss[row][c4*4] = sv;
        }
        __syncthreads();

        #pragma unroll 4
        for (int dd = 0; dd < 32; ++dd) {
            float kf[8], sf[8];
            #pragma unroll
            for (int i = 0; i < 8; ++i) kf[i] = Ks[tn + 16*i][dd];
            #pragma unroll
            for (int j = 0; j < 8; ++j) sf[j] = Ss[8*tb + j][dd];
            #pragma unroll
            for (int i = 0; i < 8; ++i)
                #pragma unroll
                for (int j = 0; j < 8; ++j)
                    acc[i][j] = fmaf(kf[i], sf[j], acc[i][j]);
        }
        __syncthreads();
    }

    // exp, partial Z, store E
    if (tid < 128) zsm[tid] = 0.f;
    __syncthreads();

    float zp[8];
    #pragma unroll
    for (int j = 0; j < 8; ++j) zp[j] = 0.f;
    #pragma unroll
    for (int i = 0; i < 8; ++i)
        #pragma unroll
        for (int j = 0; j < 8; ++j) {
            float e = __expf((acc[i][j] - 1.0f) * invT);  // logits <= 0 => e <= 1
            acc[i][j] = e;
            zp[j] += e;
        }
    #pragma unroll
    for (int j = 0; j < 8; ++j) atomicAdd(&zsm[8*tb + j], zp[j]);

    #pragma unroll
    for (int i = 0; i < 8; ++i) {
        size_t row = n0 + (size_t)(tn + 16*i);
        float4 v0 = make_float4(acc[i][0], acc[i][1], acc[i][2], acc[i][3]);
        float4 v1 = make_float4(acc[i][4], acc[i][5], acc[i][6], acc[i][7]);
        *(float4*)(g_E + row*BB + 8*tb    ) = v0;
        *(float4*)(g_E + row*BB + 8*tb + 4) = v1;
    }

    __syncthreads();
    if (tid < 128) atomicAdd(&g_Z[tid], zsm[tid]);
}

// ---------------------------------------------------------------------------
// K2: per block: chunk of n rows. W = E[n][b]/Z[b].
//     WSpart[b][d] += sum_n W * V[n][d];  new_age[n] = age[n] + sum_b W.
//     32-row tiles; 8x8 micro-tile: b_j = tbb + 16*j, d_l = tdd + 16*l.
// ---------------------------------------------------------------------------
__global__ void __launch_bounds__(256, 2)
k_pass2(const float* __restrict__ values, const float* __restrict__ age,
        float* __restrict__ out, int chunkN) {
    __shared__ float Es[32][132];
    __shared__ float Vs[32][132];
    __shared__ float zinv[128];
    __shared__ float napart[32][9];

    const int tid = threadIdx.x;
    if (tid < 128) zinv[tid] = 1.0f / g_Z[tid];
    __syncthreads();

    const int tbb = tid & 15;
    const int tdd = tid >> 4;
    const size_t base = (size_t)blockIdx.x * (size_t)chunkN;

    float acc[8][8];
    #pragma unroll
    for (int j = 0; j < 8; ++j)
        #pragma unroll
        for (int l = 0; l < 8; ++l) acc[j][l] = 0.f;

    for (int nt = 0; nt < chunkN; nt += 32) {
        const size_t n0 = base + nt;
        // load 32x128 of E (scaled by 1/Z) and V
        #pragma unroll
        for (int t = 0; t < 4; ++t) {
            int idx = tid + 256*t;           // 0..1023
            int row = idx >> 5;
            int c4  = idx & 31;
            float4 e = *(const float4*)(g_E + (n0 + row)*BB + c4*4);
            float4 z = *(const float4*)(&zinv[c4*4]);
            e.x *= z.x; e.y *= z.y; e.z *= z.z; e.w *= z.w;
            *(float4*)&Es[row][c4*4] = e;
            float4 v = *(const float4*)(values + (n0 + row)*DD + c4*4);
            *(float4*)&Vs[row][c4*4] = v;
        }
        __syncthreads();

        // new_age partial sums over b: 8 threads per row, 16 floats each
        {
            int r = tid & 31, q = tid >> 5;
            float s = 0.f;
            #pragma unroll
            for (int t = 0; t < 4; ++t) {
                float4 e = *(float4*)&Es[r][q*16 + t*4];
                s += (e.x + e.y) + (e.z + e.w);
            }
            napart[r][q] = s;
        }

        // rank-32 update
        #pragma unroll 4
        for (int n = 0; n < 32; ++n) {
            float ef[8], vf[8];
            #pragma unroll
            for (int j = 0; j < 8; ++j) ef[j] = Es[n][tbb + 16*j];
            #pragma unroll
            for (int l = 0; l < 8; ++l) vf[l] = Vs[n][tdd + 16*l];
            #pragma unroll
            for (int j = 0; j < 8; ++j)
                #pragma unroll
                for (int l = 0; l < 8; ++l)
                    acc[j][l] = fmaf(ef[j], vf[l], acc[j][l]);
        }
        __syncthreads();

        // finalize new_age for these 32 rows (napart written before the sync)
        if (tid < 32) {
            float s = 0.f;
            #pragma unroll
            for (int q = 0; q < 8; ++q) s += napart[tid][q];
            out[BB*DD + n0 + tid] = age[n0 + tid] + s;
        }
    }

    // write per-block WS partial (once)
    float* wp = g_WSpart + (size_t)blockIdx.x * (BB*DD);
    #pragma unroll
    for (int j = 0; j < 8; ++j)
        #pragma unroll
        for (int l = 0; l < 8; ++l)
            wp[(tbb + 16*j)*DD + (tdd + 16*l)] = acc[j][l];
}

// ---------------------------------------------------------------------------
// K3: reduce WS partials -> out[0 .. 16383]
// ---------------------------------------------------------------------------
__global__ void k_reduce(float* __restrict__ out, int nparts) {
    int i = blockIdx.x * blockDim.x + threadIdx.x;   // 16384 threads
    float s = 0.f;
    for (int k = 0; k < nparts; ++k)
        s += g_WSpart[(size_t)k * (BB*DD) + i];
    out[i] = s;
}

// ---------------------------------------------------------------------------
extern "C" void kernel_launch(void* const* d_in, const int* in_sizes, int n_in,
                              void* d_out, int out_size) {
    const float* st     = (const float*)d_in[0];   // [128,128]
    const float* keys   = (const float*)d_in[1];   // [N,128]
    const float* values = (const float*)d_in[2];   // [N,128]
    const float* age    = (const float*)d_in[3];   // [N]
    float* out = (float*)d_out;                    // [128*128 + N]

    const int N = in_sizes[3];
    double tt = 0.11 - log10((double)N) * 0.01;    // temperature (matches ref)
    float invT = (float)(1.0 / tt);

    k_norm<<<1, 128>>>(st);
    k_pass1<<<N / 128, 256>>>(keys, invT);
    int chunk = N / GRID2;                         // 1024 for N=2^20, mult of 32
    k_pass2<<<GRID2, 256>>>(values, age, out, chunk);
    k_reduce<<<(BB*DD) / 256, 256>>>(out, GRID2);
}

// round 3
// speedup vs baseline: 1.0975x; 1.0975x over previous
#include <cuda_runtime.h>
#include <cuda_bf16.h>
#include <mma.h>
#include <math.h>

using namespace nvcuda;

#define BB 128          // batch rows
#define DD 128          // feature dim
#define NMAX (1u<<20)   // memory slots
#define GRID2 512       // pass-2 blocks
#define RED_SLICES 8

// -------- device scratch (statically allocated; no cudaMalloc anywhere) ----
__device__ __nv_bfloat16 g_shi[BB*DD];             // state hi (row-major [b][d])
__device__ __nv_bfloat16 g_slo[BB*DD];             // state lo
__device__ float g_Z[BB];                          // softmax denominators
__device__ __nv_bfloat16 g_Ehi[(size_t)NMAX*BB];   // exp weights hi [N][B] (256 MB)
__device__ __nv_bfloat16 g_Elo[(size_t)NMAX*BB];   // exp weights lo (256 MB)
__device__ float g_WSpart[(size_t)GRID2*BB*DD];    // per-block WS partials (32 MB)
__device__ float g_red[(size_t)RED_SLICES*BB*DD];  // reduction stage-1

__device__ __forceinline__ void split2(float x, __nv_bfloat16& hi, __nv_bfloat16& lo) {
    hi = __float2bfloat16(x);
    lo = __float2bfloat16(x - __bfloat162float(hi));
}

// ---------------------------------------------------------------------------
// K0: normalize encoded_state rows, split to bf16 hi/lo, zero Z. <<<1,128>>>
// ---------------------------------------------------------------------------
__global__ void k_norm(const float* __restrict__ st) {
    int b = threadIdx.x;
    float ss = 0.f;
    #pragma unroll 8
    for (int d = 0; d < DD; ++d) { float v = st[b*DD + d]; ss += v*v; }
    float inv = 1.0f / fmaxf(sqrtf(ss), 1e-12f);
    #pragma unroll 8
    for (int d = 0; d < DD; ++d) {
        float s = st[b*DD + d] * inv;
        split2(s, g_shi[b*DD + d], g_slo[b*DD + d]);
    }
    g_Z[b] = 0.f;
}

// ---------------------------------------------------------------------------
// K1: tile of 32 keys x 128 batch.  sims = K . state^T via bf16-split wmma,
//     E = exp((s-1)*invT), store E hi/lo, accumulate Z.
//     128 threads = 4 warps; warp w: rows 16*(w>>1), cols 64*(w&1), 4 col-tiles.
// ---------------------------------------------------------------------------
__global__ void __launch_bounds__(128, 4)
k_pass1(const float* __restrict__ keys, float invT) {
    __shared__ __nv_bfloat16 Khi[32][136];
    __shared__ __nv_bfloat16 Klo[32][136];
    __shared__ float Etile[32][132];

    const int tid = threadIdx.x;
    const size_t n0 = (size_t)blockIdx.x * 32;

    // load & split 32x128 keys
    #pragma unroll
    for (int t = 0; t < 8; ++t) {
        int idx = tid + 128*t;           // 0..1023
        int row = idx >> 5;
        int c4  = idx & 31;
        float4 v = *(const float4*)(keys + (n0 + row)*DD + c4*4);
        split2(v.x, Khi[row][c4*4+0], Klo[row][c4*4+0]);
        split2(v.y, Khi[row][c4*4+1], Klo[row][c4*4+1]);
        split2(v.z, Khi[row][c4*4+2], Klo[row][c4*4+2]);
        split2(v.w, Khi[row][c4*4+3], Klo[row][c4*4+3]);
    }
    __syncthreads();

    const int wid = tid >> 5;
    const int rs  = (wid >> 1) * 16;     // row strip
    const int ch  = (wid & 1) * 64;      // col half

    wmma::fragment<wmma::accumulator, 16, 16, 16, float> acc[4];
    #pragma unroll
    for (int c = 0; c < 4; ++c) wmma::fill_fragment(acc[c], 0.f);

    #pragma unroll
    for (int k = 0; k < 8; ++k) {
        wmma::fragment<wmma::matrix_a, 16, 16, 16, __nv_bfloat16, wmma::row_major> ahi, alo;
        wmma::load_matrix_sync(ahi, &Khi[rs][k*16], 136);
        wmma::load_matrix_sync(alo, &Klo[rs][k*16], 136);
        #pragma unroll
        for (int c = 0; c < 4; ++c) {
            wmma::fragment<wmma::matrix_b, 16, 16, 16, __nv_bfloat16, wmma::col_major> bhi, blo;
            const __nv_bfloat16* bp = g_shi + (size_t)(ch + c*16)*DD + k*16;
            const __nv_bfloat16* bq = g_slo + (size_t)(ch + c*16)*DD + k*16;
            wmma::load_matrix_sync(bhi, bp, DD);
            wmma::load_matrix_sync(blo, bq, DD);
            wmma::mma_sync(acc[c], ahi, bhi, acc[c]);
            wmma::mma_sync(acc[c], ahi, blo, acc[c]);
            wmma::mma_sync(acc[c], alo, bhi, acc[c]);
        }
    }

    // elementwise exp on fragments (logits <= 0 since cosine sims <= 1)
    #pragma unroll
    for (int c = 0; c < 4; ++c) {
        #pragma unroll
        for (int t = 0; t < acc[c].num_elements; ++t)
            acc[c].x[t] = __expf((acc[c].x[t] - 1.0f) * invT);
        wmma::store_matrix_sync(&Etile[rs][ch + c*16], acc[c], 132, wmma::mem_row_major);
    }
    __syncthreads();

    // column sums -> Z ; split-store E
    float z = 0.f;
    #pragma unroll 4
    for (int r = 0; r < 32; ++r) {
        float e = Etile[r][tid];
        z += e;
        __nv_bfloat16 hi, lo;
        split2(e, hi, lo);
        g_Ehi[(n0 + r)*BB + tid] = hi;
        g_Elo[(n0 + r)*BB + tid] = lo;
    }
    atomicAdd(&g_Z[tid], z);
}

// ---------------------------------------------------------------------------
// K2: WS[b][d] += sum_n W[n][b]*V[n][d]  (W = (Ehi+Elo)/Z, split bf16)
//     new_age[n] = age[n] + sum_b W[n][b]
//     256 threads = 8 warps; warp w: output b-strip w*16, all 8 d-tiles.
// ---------------------------------------------------------------------------
__global__ void __launch_bounds__(256, 2)
k_pass2(const float* __restrict__ values, const float* __restrict__ age,
        float* __restrict__ out, int chunkN) {
    __shared__ __nv_bfloat16 Whi[32][136];
    __shared__ __nv_bfloat16 Wlo[32][136];
    __shared__ __nv_bfloat16 Vhi[32][136];
    __shared__ __nv_bfloat16 Vlo[32][136];
    __shared__ float zinv[128];

    const int tid = threadIdx.x;
    if (tid < 128) zinv[tid] = 1.0f / g_Z[tid];
    __syncthreads();

    const int wid = tid >> 5;
    const int b0  = wid * 16;
    const size_t base = (size_t)blockIdx.x * (size_t)chunkN;

    wmma::fragment<wmma::accumulator, 16, 16, 16, float> acc[8];
    #pragma unroll
    for (int c = 0; c < 8; ++c) wmma::fill_fragment(acc[c], 0.f);

    for (int nt = 0; nt < chunkN; nt += 32) {
        const size_t n0 = base + nt;

        #pragma unroll
        for (int t = 0; t < 4; ++t) {
            int idx = tid + 256*t;       // 0..1023
            int row = idx >> 5;
            int c4  = idx & 31;
            // E hi/lo: 4 consecutive bf16 each (8-byte loads)
            uint2 uh = *(const uint2*)(g_Ehi + (n0 + row)*BB + c4*4);
            uint2 ul = *(const uint2*)(g_Elo + (n0 + row)*BB + c4*4);
            __nv_bfloat162 h01 = *reinterpret_cast<const __nv_bfloat162*>(&uh.x);
            __nv_bfloat162 h23 = *reinterpret_cast<const __nv_bfloat162*>(&uh.y);
            __nv_bfloat162 l01 = *reinterpret_cast<const __nv_bfloat162*>(&ul.x);
            __nv_bfloat162 l23 = *reinterpret_cast<const __nv_bfloat162*>(&ul.y);
            float w0 = (__bfloat162float(h01.x) + __bfloat162float(l01.x)) * zinv[c4*4+0];
            float w1 = (__bfloat162float(h01.y) + __bfloat162float(l01.y)) * zinv[c4*4+1];
            float w2 = (__bfloat162float(h23.x) + __bfloat162float(l23.x)) * zinv[c4*4+2];
            float w3 = (__bfloat162float(h23.y) + __bfloat162float(l23.y)) * zinv[c4*4+3];
            split2(w0, Whi[row][c4*4+0], Wlo[row][c4*4+0]);
            split2(w1, Whi[row][c4*4+1], Wlo[row][c4*4+1]);
            split2(w2, Whi[row][c4*4+2], Wlo[row][c4*4+2]);
            split2(w3, Whi[row][c4*4+3], Wlo[row][c4*4+3]);
            // values split
            float4 v = *(const float4*)(values + (n0 + row)*DD + c4*4);
            split2(v.x, Vhi[row][c4*4+0], Vlo[row][c4*4+0]);
            split2(v.y, Vhi[row][c4*4+1], Vlo[row][c4*4+1]);
            split2(v.z, Vhi[row][c4*4+2], Vlo[row][c4*4+2]);
            split2(v.w, Vhi[row][c4*4+3], Vlo[row][c4*4+3]);

            // new_age: the 32 threads with this row are lanes of one warp
            float s = w0 + w1 + w2 + w3;
            #pragma unroll
            for (int off = 16; off > 0; off >>= 1)
                s += __shfl_xor_sync(0xffffffffu, s, off);
            if (c4 == 0)
                out[BB*DD + n0 + row] = age[n0 + row] + s;
        }
        __syncthreads();

        #pragma unroll
        for (int k = 0; k < 2; ++k) {
            wmma::fragment<wmma::matrix_a, 16, 16, 16, __nv_bfloat16, wmma::col_major> ahi, alo;
            wmma::load_matrix_sync(ahi, &Whi[k*16][b0], 136);
            wmma::load_matrix_sync(alo, &Wlo[k*16][b0], 136);
            #pragma unroll
            for (int c = 0; c < 8; ++c) {
                wmma::fragment<wmma::matrix_b, 16, 16, 16, __nv_bfloat16, wmma::row_major> bhi, blo;
                wmma::load_matrix_sync(bhi, &Vhi[k*16][c*16], 136);
                wmma::load_matrix_sync(blo, &Vlo[k*16][c*16], 136);
                wmma::mma_sync(acc[c], ahi, bhi, acc[c]);
                wmma::mma_sync(acc[c], ahi, blo, acc[c]);
                wmma::mma_sync(acc[c], alo, bhi, acc[c]);
            }
        }
        __syncthreads();
    }

    float* wp = g_WSpart + (size_t)blockIdx.x * (BB*DD);
    #pragma unroll
    for (int c = 0; c < 8; ++c)
        wmma::store_matrix_sync(wp + b0*DD + c*16, acc[c], DD, wmma::mem_row_major);
}

// ---------------------------------------------------------------------------
// K3a: stage-1 reduce: 512 partials -> 8 slice-sums per output element
// ---------------------------------------------------------------------------
__global__ void k_reduce1(void) {
    int gid = blockIdx.x * blockDim.x + threadIdx.x;    // 131072 threads
    int slice = gid >> 14;
    int i = gid & 16383;
    const int per = GRID2 / RED_SLICES;                 // 64
    float s = 0.f;
    #pragma unroll 4
    for (int k = 0; k < per; ++k)
        s += g_WSpart[(size_t)(slice*per + k) * (BB*DD) + i];
    g_red[(size_t)slice * (BB*DD) + i] = s;
}

// K3b: stage-2 reduce -> out[0..16383]
__global__ void k_reduce2(float* __restrict__ out) {
    int i = blockIdx.x * blockDim.x + threadIdx.x;      // 16384 threads
    float s = 0.f;
    #pragma unroll
    for (int k = 0; k < RED_SLICES; ++k)
        s += g_red[(size_t)k * (BB*DD) + i];
    out[i] = s;
}

// ---------------------------------------------------------------------------
extern "C" void kernel_launch(void* const* d_in, const int* in_sizes, int n_in,
                              void* d_out, int out_size) {
    const float* st     = (const float*)d_in[0];   // [128,128]
    const float* keys   = (const float*)d_in[1];   // [N,128]
    const float* values = (const float*)d_in[2];   // [N,128]
    const float* age    = (const float*)d_in[3];   // [N]
    float* out = (float*)d_out;                    // [128*128 + N]

    const int N = in_sizes[3];
    double tt = 0.11 - log10((double)N) * 0.01;    // temperature (matches ref)
    float invT = (float)(1.0 / tt);

    k_norm<<<1, 128>>>(st);
    k_pass1<<<N / 32, 128>>>(keys, invT);
    int chunk = N / GRID2;                         // 2048 for N=2^20
    k_pass2<<<GRID2, 256>>>(values, age, out, chunk);
    k_reduce1<<<512, 256>>>();
    k_reduce2<<<64, 256>>>(out);
}

// round 4
// speedup vs baseline: 1.6648x; 1.5168x over previous
#include <cuda_runtime.h>
#include <cuda_bf16.h>
#include <mma.h>
#include <math.h>

using namespace nvcuda;

#define BB 128          // batch rows
#define DD 128          // feature dim
#define NMAX (1u<<20)   // memory slots
#define GRID2 512       // pass-2 blocks
#define RED_SLICES 8

// -------- device scratch (statically allocated; no cudaMalloc anywhere) ----
__device__ __nv_bfloat16 g_shi[BB*DD];             // state hi (row-major [b][d])
__device__ __nv_bfloat16 g_slo[BB*DD];             // state lo
__device__ float g_Z[BB];                          // softmax denominators
__device__ __nv_bfloat16 g_Ehi[(size_t)NMAX*BB];   // exp weights hi [N][B] (256 MB)
__device__ __nv_bfloat16 g_Elo[(size_t)NMAX*BB];   // exp weights lo (256 MB)
__device__ float g_WSpart[(size_t)GRID2*BB*DD];    // per-block UNNORMALIZED WS partials
__device__ float g_red[(size_t)RED_SLICES*BB*DD];  // reduction stage-1

__device__ __forceinline__ void split2(float x, __nv_bfloat16& hi, __nv_bfloat16& lo) {
    hi = __float2bfloat16(x);
    lo = __float2bfloat16(x - __bfloat162float(hi));
}

// ---------------------------------------------------------------------------
// K0: normalize encoded_state rows, split to bf16 hi/lo, zero Z. <<<1,128>>>
// ---------------------------------------------------------------------------
__global__ void k_norm(const float* __restrict__ st) {
    int b = threadIdx.x;
    float ss = 0.f;
    #pragma unroll 8
    for (int d = 0; d < DD; ++d) { float v = st[b*DD + d]; ss += v*v; }
    float inv = 1.0f / fmaxf(sqrtf(ss), 1e-12f);
    #pragma unroll 8
    for (int d = 0; d < DD; ++d) {
        float s = st[b*DD + d] * inv;
        split2(s, g_shi[b*DD + d], g_slo[b*DD + d]);
    }
    g_Z[b] = 0.f;
}

// ---------------------------------------------------------------------------
// K1: 64 keys x 128 batch per block, 256 threads (8 warps).
//     State hi/lo staged ONCE in smem; keys split in smem; split-bf16 wmma;
//     E = exp((s-1)*invT) on register fragments; store E hi/lo; Z atomics.
//     Warp w: rows 16*(w>>1), cols 64*(w&1).
// ---------------------------------------------------------------------------
#define SM1_BYTES (2*128*136*2 + 2*64*136*2)   // Shi,Slo + Khi,Klo = 104448
__global__ void __launch_bounds__(256, 2)
k_pass1(const float* __restrict__ keys, float invT) {
    extern __shared__ char smraw[];
    __nv_bfloat16* Shi = (__nv_bfloat16*)smraw;            // [128][136]
    __nv_bfloat16* Slo = Shi + 128*136;
    __nv_bfloat16* Khi = Slo + 128*136;                    // [64][136]
    __nv_bfloat16* Klo = Khi + 64*136;
    float* Etile = (float*)Khi;                            // [64][132] (reuse after MMA)

    const int tid = threadIdx.x;
    const int wid = tid >> 5;
    const size_t n0 = (size_t)blockIdx.x * 64;

    // stage state hi/lo (8 bf16 per uint4)
    #pragma unroll
    for (int t = 0; t < 8; ++t) {
        int idx = tid + 256*t;           // 0..2047
        int r = idx >> 4, q = idx & 15;
        *(uint4*)(Shi + r*136 + q*8) = *(const uint4*)(g_shi + r*DD + q*8);
        *(uint4*)(Slo + r*136 + q*8) = *(const uint4*)(g_slo + r*DD + q*8);
    }
    // load + split keys 64x128
    #pragma unroll
    for (int t = 0; t < 8; ++t) {
        int idx = tid + 256*t;           // 0..2047
        int r = idx >> 5, c4 = idx & 31;
        float4 v = *(const float4*)(keys + (n0 + r)*DD + c4*4);
        split2(v.x, Khi[r*136 + c4*4+0], Klo[r*136 + c4*4+0]);
        split2(v.y, Khi[r*136 + c4*4+1], Klo[r*136 + c4*4+1]);
        split2(v.z, Khi[r*136 + c4*4+2], Klo[r*136 + c4*4+2]);
        split2(v.w, Khi[r*136 + c4*4+3], Klo[r*136 + c4*4+3]);
    }
    __syncthreads();

    const int rs = (wid >> 1) * 16;      // row strip within 64
    const int ch = (wid & 1) * 64;       // col half

    wmma::fragment<wmma::accumulator, 16, 16, 16, float> acc[4];
    #pragma unroll
    for (int c = 0; c < 4; ++c) wmma::fill_fragment(acc[c], 0.f);

    #pragma unroll
    for (int k = 0; k < 8; ++k) {
        wmma::fragment<wmma::matrix_a, 16, 16, 16, __nv_bfloat16, wmma::row_major> ahi, alo;
        wmma::load_matrix_sync(ahi, Khi + rs*136 + k*16, 136);
        wmma::load_matrix_sync(alo, Klo + rs*136 + k*16, 136);
        #pragma unroll
        for (int c = 0; c < 4; ++c) {
            wmma::fragment<wmma::matrix_b, 16, 16, 16, __nv_bfloat16, wmma::col_major> bhi, blo;
            wmma::load_matrix_sync(bhi, Shi + (ch + c*16)*136 + k*16, 136);
            wmma::load_matrix_sync(blo, Slo + (ch + c*16)*136 + k*16, 136);
            wmma::mma_sync(acc[c], ahi, bhi, acc[c]);
            wmma::mma_sync(acc[c], ahi, blo, acc[c]);
            wmma::mma_sync(acc[c], alo, bhi, acc[c]);
        }
    }

    // exp on register fragments (logits <= 0 since cosine sims <= 1)
    #pragma unroll
    for (int c = 0; c < 4; ++c)
        #pragma unroll
        for (int t = 0; t < acc[c].num_elements; ++t)
            acc[c].x[t] = __expf((acc[c].x[t] - 1.0f) * invT);

    __syncthreads();   // all MMA reads of Khi/Klo done before Etile overwrite
    #pragma unroll
    for (int c = 0; c < 4; ++c)
        wmma::store_matrix_sync(Etile + rs*132 + ch + c*16, acc[c], 132, wmma::mem_row_major);
    __syncthreads();

    // column sums -> Z ; split-store E
    if (tid < 128) {
        float z = 0.f;
        #pragma unroll 4
        for (int r = 0; r < 64; ++r) {
            float e = Etile[r*132 + tid];
            z += e;
            __nv_bfloat16 hi, lo;
            split2(e, hi, lo);
            g_Ehi[(n0 + r)*BB + tid] = hi;
            g_Elo[(n0 + r)*BB + tid] = lo;
        }
        atomicAdd(&g_Z[tid], z);
    }
}

// ---------------------------------------------------------------------------
// K2: WS_un[b][d] += sum_n E[n][b]*V[n][d]   (E = Ehi+Elo used DIRECTLY as
//     the split operands; no decode, no re-split). Normalization by 1/Z is
//     folded into the final reduce. new_age[n] = age[n] + sum_b E[n][b]/Z[b].
//     256 threads = 8 warps; warp w: b-strip w*16, all 8 d-tiles.
// ---------------------------------------------------------------------------
__global__ void __launch_bounds__(256, 2)
k_pass2(const float* __restrict__ values, const float* __restrict__ age,
        float* __restrict__ out, int chunkN) {
    __shared__ __nv_bfloat16 Ehs[32*136];
    __shared__ __nv_bfloat16 Els[32*136];
    __shared__ __nv_bfloat16 Vhs[32*136];
    __shared__ __nv_bfloat16 Vls[32*136];
    __shared__ float zinv[128];

    const int tid = threadIdx.x;
    if (tid < 128) zinv[tid] = 1.0f / g_Z[tid];
    __syncthreads();

    const int wid = tid >> 5;
    const int b0  = wid * 16;
    const size_t base = (size_t)blockIdx.x * (size_t)chunkN;

    wmma::fragment<wmma::accumulator, 16, 16, 16, float> acc[8];
    #pragma unroll
    for (int c = 0; c < 8; ++c) wmma::fill_fragment(acc[c], 0.f);

    for (int nt = 0; nt < chunkN; nt += 32) {
        const size_t n0 = base + nt;

        // E tiles: raw uint4 copies + age partials on the fly
        #pragma unroll
        for (int t = 0; t < 2; ++t) {
            int idx = tid + 256*t;        // 0..511
            int row = idx >> 4, g = idx & 15;
            uint4 uh = *(const uint4*)(g_Ehi + (n0 + row)*BB + g*8);
            uint4 ul = *(const uint4*)(g_Elo + (n0 + row)*BB + g*8);
            *(uint4*)(Ehs + row*136 + g*8) = uh;
            *(uint4*)(Els + row*136 + g*8) = ul;
            // age partial: sum over these 8 b of (hi+lo)*zinv[b]
            const __nv_bfloat162* h2 = (const __nv_bfloat162*)&uh;
            const __nv_bfloat162* l2 = (const __nv_bfloat162*)&ul;
            float s = 0.f;
            #pragma unroll
            for (int p = 0; p < 4; ++p) {
                float2 hf = __bfloat1622float2(h2[p]);
                float2 lf = __bfloat1622float2(l2[p]);
                s = fmaf(hf.x + lf.x, zinv[g*8 + 2*p],     s);
                s = fmaf(hf.y + lf.y, zinv[g*8 + 2*p + 1], s);
            }
            #pragma unroll
            for (int off = 8; off > 0; off >>= 1)
                s += __shfl_xor_sync(0xffffffffu, s, off);
            if (g == 0)
                out[BB*DD + n0 + row] = age[n0 + row] + s;
        }
        // V tiles: load + split
        #pragma unroll
        for (int t = 0; t < 4; ++t) {
            int idx = tid + 256*t;        // 0..1023
            int row = idx >> 5, c4 = idx & 31;
            float4 v = *(const float4*)(values + (n0 + row)*DD + c4*4);
            split2(v.x, Vhs[row*136 + c4*4+0], Vls[row*136 + c4*4+0]);
            split2(v.y, Vhs[row*136 + c4*4+1], Vls[row*136 + c4*4+1]);
            split2(v.z, Vhs[row*136 + c4*4+2], Vls[row*136 + c4*4+2]);
            split2(v.w, Vhs[row*136 + c4*4+3], Vls[row*136 + c4*4+3]);
        }
        __syncthreads();

        #pragma unroll
        for (int k = 0; k < 2; ++k) {
            wmma::fragment<wmma::matrix_a, 16, 16, 16, __nv_bfloat16, wmma::col_major> ahi, alo;
            wmma::load_matrix_sync(ahi, Ehs + k*16*136 + b0, 136);
            wmma::load_matrix_sync(alo, Els + k*16*136 + b0, 136);
            #pragma unroll
            for (int c = 0; c < 8; ++c) {
                wmma::fragment<wmma::matrix_b, 16, 16, 16, __nv_bfloat16, wmma::row_major> bhi, blo;
                wmma::load_matrix_sync(bhi, Vhs + k*16*136 + c*16, 136);
                wmma::load_matrix_sync(blo, Vls + k*16*136 + c*16, 136);
                wmma::mma_sync(acc[c], ahi, bhi, acc[c]);
                wmma::mma_sync(acc[c], ahi, blo, acc[c]);
                wmma::mma_sync(acc[c], alo, bhi, acc[c]);
            }
        }
        __syncthreads();
    }

    float* wp = g_WSpart + (size_t)blockIdx.x * (BB*DD);
    #pragma unroll
    for (int c = 0; c < 8; ++c)
        wmma::store_matrix_sync(wp + b0*DD + c*16, acc[c], DD, wmma::mem_row_major);
}

// ---------------------------------------------------------------------------
// K3a: stage-1 reduce: 512 partials -> 8 slice-sums per output element
// ---------------------------------------------------------------------------
__global__ void k_reduce1(void) {
    int gid = blockIdx.x * blockDim.x + threadIdx.x;    // 131072 threads
    int slice = gid >> 14;
    int i = gid & 16383;
    const int per = GRID2 / RED_SLICES;                 // 64
    float s = 0.f;
    #pragma unroll 4
    for (int k = 0; k < per; ++k)
        s += g_WSpart[(size_t)(slice*per + k) * (BB*DD) + i];
    g_red[(size_t)slice * (BB*DD) + i] = s;
}

// K3b: stage-2 reduce + softmax normalization -> out[0..16383]
__global__ void k_reduce2(float* __restrict__ out) {
    int i = blockIdx.x * blockDim.x + threadIdx.x;      // 16384 threads
    float s = 0.f;
    #pragma unroll
    for (int k = 0; k < RED_SLICES; ++k)
        s += g_red[(size_t)k * (BB*DD) + i];
    out[i] = s / g_Z[i >> 7];
}

// ---------------------------------------------------------------------------
extern "C" void kernel_launch(void* const* d_in, const int* in_sizes, int n_in,
                              void* d_out, int out_size) {
    const float* st     = (const float*)d_in[0];   // [128,128]
    const float* keys   = (const float*)d_in[1];   // [N,128]
    const float* values = (const float*)d_in[2];   // [N,128]
    const float* age    = (const float*)d_in[3];   // [N]
    float* out = (float*)d_out;                    // [128*128 + N]

    const int N = in_sizes[3];
    double tt = 0.11 - log10((double)N) * 0.01;    // temperature (matches ref)
    float invT = (float)(1.0 / tt);

    cudaFuncSetAttribute(k_pass1, cudaFuncAttributeMaxDynamicSharedMemorySize, SM1_BYTES);

    k_norm<<<1, 128>>>(st);
    k_pass1<<<N / 64, 256, SM1_BYTES>>>(keys, invT);
    int chunk = N / GRID2;                         // 2048 for N=2^20
    k_pass2<<<GRID2, 256>>>(values, age, out, chunk);
    k_reduce1<<<512, 256>>>();
    k_reduce2<<<64, 256>>>(out);
}

// round 6
// speedup vs baseline: 2.8038x; 1.6842x over previous
#include <cuda_runtime.h>
#include <cuda_bf16.h>
#include <math.h>
#include <stdint.h>

#define BB 128
#define DD 128
#define NMAX (1u<<20)
#define GRID2 1024
#define RED_SLICES 8

// smem layout (bytes):
//   Kt:  [buf 2][split 2][64 rows][136 bf16]  -> 2*2*64*136*2 = 69632   @ 0
//   Vt:  same geometry                         -> 69632               @ 69632
//   Sls: state-lo persistent [128][136] bf16   -> 34816               @ 139264
//   (state-hi staged transiently at offset 0, consumed into registers pre-loop)
#define KT_OFF   0
#define VT_OFF   69632
#define SLS_OFF  139264
#define SM_BYTES 174080
#define TILE_STRIDE 272            // 136 bf16 row stride in bytes

// -------- device scratch ----------------------------------------------------
__device__ __nv_bfloat16 g_shi[BB*DD];
__device__ __nv_bfloat16 g_slo[BB*DD];
__device__ float g_Z[BB];
__device__ __nv_bfloat16 g_P[(size_t)NMAX*BB];     // P hi, [n][permuted b] (256 MB)
__device__ float g_WSpart[(size_t)GRID2*BB*DD];
__device__ float g_red[(size_t)RED_SLICES*BB*DD];

// -------- helpers ------------------------------------------------------------
__device__ __forceinline__ uint32_t smem_u32(const void* p) {
    uint32_t a;
    asm("{ .reg .u64 t; cvta.to.shared.u64 t, %1; cvt.u32.u64 %0, t; }" : "=r"(a) : "l"(p));
    return a;
}
// pack two f32 -> bf16x2 (hi arg in high half, lo arg in low half)
__device__ __forceinline__ uint32_t cvt2(float hi, float lo) {
    uint32_t r;
    asm("cvt.rn.bf16x2.f32 %0, %1, %2;" : "=r"(r) : "f"(hi), "f"(lo));
    return r;
}
__device__ __forceinline__ void split4(float4 v, uint2& h, uint2& lo) {
    uint32_t h0 = cvt2(v.y, v.x);
    uint32_t h1 = cvt2(v.w, v.z);
    float f0 = __uint_as_float(h0 << 16);
    float f1 = __uint_as_float(h0 & 0xffff0000u);
    float f2 = __uint_as_float(h1 << 16);
    float f3 = __uint_as_float(h1 & 0xffff0000u);
    h  = make_uint2(h0, h1);
    lo = make_uint2(cvt2(v.y - f1, v.x - f0), cvt2(v.w - f3, v.z - f2));
}
__device__ __forceinline__ void split2g(float x, __nv_bfloat16& hi, __nv_bfloat16& lo) {
    hi = __float2bfloat16(x);
    lo = __float2bfloat16(x - __bfloat162float(hi));
}

#define LDSM4(d, a_) asm volatile( \
    "ldmatrix.sync.aligned.m8n8.x4.shared.b16 {%0,%1,%2,%3}, [%4];" \
    : "=r"((d)[0]), "=r"((d)[1]), "=r"((d)[2]), "=r"((d)[3]) : "r"(a_))
#define LDSM4T(d, a_) asm volatile( \
    "ldmatrix.sync.aligned.m8n8.x4.trans.shared.b16 {%0,%1,%2,%3}, [%4];" \
    : "=r"((d)[0]), "=r"((d)[1]), "=r"((d)[2]), "=r"((d)[3]) : "r"(a_))
#define MMA16816(C, a0_,a1_,a2_,a3_, b0_,b1_) asm volatile( \
    "mma.sync.aligned.m16n8k16.row.col.f32.bf16.bf16.f32 " \
    "{%0,%1,%2,%3},{%4,%5,%6,%7},{%8,%9},{%0,%1,%2,%3};" \
    : "+f"((C)[0]), "+f"((C)[1]), "+f"((C)[2]), "+f"((C)[3]) \
    : "r"(a0_), "r"(a1_), "r"(a2_), "r"(a3_), "r"(b0_), "r"(b1_))

// ---------------------------------------------------------------------------
// K0: normalize state, split hi/lo, zero Z. <<<1,128>>>
// ---------------------------------------------------------------------------
__global__ void k_norm(const float* __restrict__ st) {
    int b = threadIdx.x;
    float ss = 0.f;
    #pragma unroll 8
    for (int d = 0; d < DD; ++d) { float v = st[b*DD + d]; ss += v*v; }
    float inv = 1.0f / fmaxf(sqrtf(ss), 1e-12f);
    #pragma unroll 8
    for (int d = 0; d < DD; ++d)
        split2g(st[b*DD + d] * inv, g_shi[b*DD + d], g_slo[b*DD + d]);
    g_Z[b] = 0.f;
}

// ---------------------------------------------------------------------------
// producer staging: K/V chunk (64 rows x 128 d) -> split bf16 tiles
// ---------------------------------------------------------------------------
__device__ __forceinline__ void stage_kv(char* sm, const float* keys, const float* values,
                                         size_t n0, int buf, int ptid) {
    char* kh = sm + KT_OFF + buf*34816;
    char* vh = sm + VT_OFF + buf*34816;
    const float4* ks = (const float4*)(keys   + n0*DD);
    const float4* vs = (const float4*)(values + n0*DD);
    #pragma unroll
    for (int it = 0; it < 32; ++it) {
        int idx = ptid + 64*it;
        int r = idx >> 5, c4 = idx & 31;
        uint32_t off = (uint32_t)r*TILE_STRIDE + c4*8;
        uint2 h, lo;
        split4(ks[idx], h, lo);
        *(uint2*)(kh + off) = h;  *(uint2*)(kh + 17408 + off) = lo;
        split4(vs[idx], h, lo);
        *(uint2*)(vh + off) = h;  *(uint2*)(vh + 17408 + off) = lo;
    }
}

// ---------------------------------------------------------------------------
// Fused kernel: S = state.K^T -> P = exp -> WS += P.V ; store Phi ; Z atomics.
// 320 threads: warps 0-7 = MMA consumers (warp w owns b rows 16w..16w+15),
//              warps 8-9 = producers (double-buffered K/V staging).
// ---------------------------------------------------------------------------
__global__ void __launch_bounds__(320, 1)
k_fused(const float* __restrict__ keys, const float* __restrict__ values,
        float invT, int chunkN) {
    extern __shared__ char sm[];
    const uint32_t sb = smem_u32(sm);
    const int tid = threadIdx.x;
    const size_t base = (size_t)blockIdx.x * (size_t)chunkN;
    const int nch = chunkN >> 6;

    // stage state: hi transient @0 (eaten into regs), lo persistent @SLS_OFF
    for (int idx = tid; idx < 2048; idx += 320) {
        int r = idx >> 4, q = idx & 15;
        *(uint4*)(sm + (uint32_t)r*TILE_STRIDE + q*16)          = *(const uint4*)(g_shi + r*DD + q*8);
        *(uint4*)(sm + SLS_OFF + (uint32_t)r*TILE_STRIDE + q*16) = *(const uint4*)(g_slo + r*DD + q*8);
    }
    __syncthreads();

    if (tid < 256) {
        // ===================== consumer =====================
        const int w = tid >> 5, l = tid & 31, g = l >> 2, t = l & 3;
        const uint32_t alane = (uint32_t)(16*w + (l & 15))*TILE_STRIDE + 16*(l >> 4);

        uint32_t AH[8][4];
        #pragma unroll
        for (int k = 0; k < 8; ++k) LDSM4(AH[k], sb + alane + 32*k);
        __syncthreads();   // state-hi consumed; producers may overwrite
        __syncthreads();   // chunk 0 staged

        float WS[16][4];
        #pragma unroll
        for (int f = 0; f < 16; ++f)
            #pragma unroll
            for (int i = 0; i < 4; ++i) WS[f][i] = 0.f;
        float zr0 = 0.f, zr1 = 0.f;

        const uint32_t slsb = sb + SLS_OFF + alane;
        const uint32_t b1lane = (uint32_t)(l & 7)*TILE_STRIDE + 16*(l >> 3);  // GEMM1 B
        const uint32_t b2lane = (uint32_t)l*TILE_STRIDE;                      // GEMM2 B (trans)

        #pragma unroll 1
        for (int c = 0; c < nch; ++c) {
            const int buf = c & 1;
            const uint32_t kh = sb + KT_OFF + buf*34816, klo = kh + 17408;
            const uint32_t vh = sb + VT_OFF + buf*34816, vlo = vh + 17408;

            // ---- GEMM1: S[16 b][64 n], split bf16 (3 products) ----
            float S[8][4];
            #pragma unroll
            for (int j = 0; j < 8; ++j)
                #pragma unroll
                for (int i = 0; i < 4; ++i) S[j][i] = 0.f;

            #pragma unroll
            for (int k2 = 0; k2 < 4; ++k2) {
                uint32_t AL0[4], AL1[4];
                LDSM4(AL0, slsb + 64*k2);
                LDSM4(AL1, slsb + 64*k2 + 32);
                #pragma unroll
                for (int j = 0; j < 8; ++j) {
                    uint32_t ba = b1lane + (uint32_t)j*8*TILE_STRIDE + 64*k2;
                    uint32_t bh[4], bl[4];
                    LDSM4(bh, kh  + ba);
                    LDSM4(bl, klo + ba);
                    MMA16816(S[j], AH[2*k2][0],AH[2*k2][1],AH[2*k2][2],AH[2*k2][3], bh[0], bh[1]);
                    MMA16816(S[j], AH[2*k2][0],AH[2*k2][1],AH[2*k2][2],AH[2*k2][3], bl[0], bl[1]);
                    MMA16816(S[j], AL0[0],AL0[1],AL0[2],AL0[3],                     bh[0], bh[1]);
                    MMA16816(S[j], AH[2*k2+1][0],AH[2*k2+1][1],AH[2*k2+1][2],AH[2*k2+1][3], bh[2], bh[3]);
                    MMA16816(S[j], AH[2*k2+1][0],AH[2*k2+1][1],AH[2*k2+1][2],AH[2*k2+1][3], bl[2], bl[3]);
                    MMA16816(S[j], AL1[0],AL1[1],AL1[2],AL1[3],                     bh[2], bh[3]);
                }
            }

            // ---- exp, split P, store Phi, Z partials ----
            uint32_t PH01[8], PH23[8], PL01[8], PL23[8];
            const size_t nb = base + (size_t)c*64;
            #pragma unroll
            for (int j = 0; j < 8; ++j) {
                float p0 = __expf((S[j][0] - 1.0f) * invT);
                float p1 = __expf((S[j][1] - 1.0f) * invT);
                float p2 = __expf((S[j][2] - 1.0f) * invT);
                float p3 = __expf((S[j][3] - 1.0f) * invT);
                zr0 += p0 + p1;  zr1 += p2 + p3;
                uint32_t h01 = cvt2(p1, p0), h23 = cvt2(p3, p2);
                PH01[j] = h01;  PH23[j] = h23;
                PL01[j] = cvt2(p1 - __uint_as_float(h01 & 0xffff0000u),
                               p0 - __uint_as_float(h01 << 16));
                PL23[j] = cvt2(p3 - __uint_as_float(h23 & 0xffff0000u),
                               p2 - __uint_as_float(h23 << 16));
                size_t n = nb + 8*j + 2*t;
                *(uint32_t*)(g_P + n*BB     + 16*w + 2*g) = __byte_perm(h01, h23, 0x5410);
                *(uint32_t*)(g_P + (n+1)*BB + 16*w + 2*g) = __byte_perm(h01, h23, 0x7632);
            }

            // ---- GEMM2: WS[16 b][128 d] += P . V  (P regs as A; 3 products) ----
            #pragma unroll
            for (int f = 0; f < 16; ++f) {
                #pragma unroll
                for (int s2 = 0; s2 < 2; ++s2) {
                    uint32_t va = b2lane + (uint32_t)s2*32*TILE_STRIDE + 16*f;
                    uint32_t bh[4], bl[4];
                    LDSM4T(bh, vh  + va);
                    LDSM4T(bl, vlo + va);
                    #pragma unroll
                    for (int ss = 0; ss < 2; ++ss) {
                        int s = 2*s2 + ss;
                        MMA16816(WS[f], PH01[2*s],PH23[2*s],PH01[2*s+1],PH23[2*s+1], bh[2*ss], bh[2*ss+1]);
                        MMA16816(WS[f], PH01[2*s],PH23[2*s],PH01[2*s+1],PH23[2*s+1], bl[2*ss], bl[2*ss+1]);
                        MMA16816(WS[f], PL01[2*s],PL23[2*s],PL01[2*s+1],PL23[2*s+1], bh[2*ss], bh[2*ss+1]);
                    }
                }
            }
            __syncthreads();
        }

        // ---- Z reduce + atomics ----
        zr0 += __shfl_xor_sync(0xffffffffu, zr0, 1);
        zr0 += __shfl_xor_sync(0xffffffffu, zr0, 2);
        zr1 += __shfl_xor_sync(0xffffffffu, zr1, 1);
        zr1 += __shfl_xor_sync(0xffffffffu, zr1, 2);
        if (t == 0) {
            atomicAdd(&g_Z[16*w + g],     zr0);
            atomicAdd(&g_Z[16*w + g + 8], zr1);
        }
        // ---- WS partial out ----
        float* wp = g_WSpart + (size_t)blockIdx.x*(BB*DD);
        #pragma unroll
        for (int f = 0; f < 16; ++f) {
            *(float2*)(wp + (16*w + g)*DD     + 8*f + 2*t) = make_float2(WS[f][0], WS[f][1]);
            *(float2*)(wp + (16*w + g + 8)*DD + 8*f + 2*t) = make_float2(WS[f][2], WS[f][3]);
        }
    } else {
        // ===================== producer =====================
        const int ptid = tid - 256;   // 0..63
        __syncthreads();              // consumers eat state-hi frags
        stage_kv(sm, keys, values, base, 0, ptid);
        __syncthreads();              // chunk 0 ready
        #pragma unroll 1
        for (int c = 0; c < nch; ++c) {
            if (c + 1 < nch)
                stage_kv(sm, keys, values, base + (size_t)(c+1)*64, (c+1) & 1, ptid);
            __syncthreads();
        }
    }
}

// ---------------------------------------------------------------------------
// Age: new_age[n] = age[n] + sum_b Phi[n][slot(b)] * (1/Z[b]).
// g_P slot permutation: p -> b = 16*(p/16) + (p%16)/2 + 8*(p%2).
// ---------------------------------------------------------------------------
__global__ void k_age(const float* __restrict__ age, float* __restrict__ out) {
    __shared__ float zp[128];
    const int tid = threadIdx.x;
    if (tid < 128) {
        int wq = tid >> 4, q = tid & 15;
        zp[tid] = 1.0f / g_Z[16*wq + (q >> 1) + 8*(q & 1)];
    }
    __syncthreads();
    const int warp = tid >> 5, l = tid & 31;
    const size_t n0 = (size_t)blockIdx.x*64 + warp*8;
    float z0 = zp[4*l], z1 = zp[4*l+1], z2 = zp[4*l+2], z3 = zp[4*l+3];
    #pragma unroll
    for (int r = 0; r < 8; ++r) {
        size_t n = n0 + r;
        uint2 u = *(const uint2*)(g_P + n*BB + 4*l);
        __nv_bfloat162 p01 = *(__nv_bfloat162*)&u.x;
        __nv_bfloat162 p23 = *(__nv_bfloat162*)&u.y;
        float s = __bfloat162float(p01.x)*z0 + __bfloat162float(p01.y)*z1
                + __bfloat162float(p23.x)*z2 + __bfloat162float(p23.y)*z3;
        #pragma unroll
        for (int off = 16; off > 0; off >>= 1)
            s += __shfl_xor_sync(0xffffffffu, s, off);
        if (l == 0) out[BB*DD + n] = age[n] + s;
    }
}

// ---------------------------------------------------------------------------
// two-stage WS reduce; 1/Z folded at the end
// ---------------------------------------------------------------------------
__global__ void k_reduce1(void) {
    int gid = blockIdx.x * blockDim.x + threadIdx.x;    // 131072
    int slice = gid >> 14;
    int i = gid & 16383;
    const int per = GRID2 / RED_SLICES;                 // 128
    float s = 0.f;
    #pragma unroll 4
    for (int k = 0; k < per; ++k)
        s += g_WSpart[(size_t)(slice*per + k) * (BB*DD) + i];
    g_red[(size_t)slice * (BB*DD) + i] = s;
}
__global__ void k_reduce2(float* __restrict__ out) {
    int i = blockIdx.x * blockDim.x + threadIdx.x;      // 16384
    float s = 0.f;
    #pragma unroll
    for (int k = 0; k < RED_SLICES; ++k)
        s += g_red[(size_t)k * (BB*DD) + i];
    out[i] = s / g_Z[i >> 7];
}

// ---------------------------------------------------------------------------
extern "C" void kernel_launch(void* const* d_in, const int* in_sizes, int n_in,
                              void* d_out, int out_size) {
    const float* st     = (const float*)d_in[0];
    const float* keys   = (const float*)d_in[1];
    const float* values = (const float*)d_in[2];
    const float* age    = (const float*)d_in[3];
    float* out = (float*)d_out;

    const int N = in_sizes[3];
    double tt = 0.11 - log10((double)N) * 0.01;
    float invT = (float)(1.0 / tt);

    cudaFuncSetAttribute(k_fused, cudaFuncAttributeMaxDynamicSharedMemorySize, SM_BYTES);

    k_norm<<<1, 128>>>(st);
    k_fused<<<GRID2, 320, SM_BYTES>>>(keys, values, invT, N / GRID2);
    k_age<<<N / 64, 256>>>(age, out);
    k_reduce1<<<512, 256>>>();
    k_reduce2<<<64, 256>>>(out);
}